// round 1
// baseline (speedup 1.0000x reference)
#include <cuda_runtime.h>

#define NMAX 50000
#define NG 512

// ---- scratch (static __device__: no allocation allowed) ----
__device__ float    g_agg[NMAX * 64];     // GIN aggregation result
__device__ float    g_h[NMAX * 64];       // hidden after Linear1
__device__ float    g_stats[128];         // [0:64) sum, [64:128) sumsq
__device__ float    g_scale[128];         // [0:64) a = gamma*rstd, [64:128) shift
__device__ float    g_add[NG * 64];       // segment sum pool
__device__ unsigned g_max[NG * 64];       // segment max pool (relu>=0 -> uint order ok)
__device__ int      g_isI32;              // 1 if indices are int32, 0 if int64

// ============================================================
// K0: init agg = x, zero stats & pools, probe index dtype
// ============================================================
__global__ void k_init(const float* __restrict__ x, const int* __restrict__ ei32, int n4) {
    int tid = blockIdx.x * blockDim.x + threadIdx.x;
    if (tid == 0) {
        // If edge_index is int64 (values < 50000), every odd 32-bit word is 0.
        // If int32, odd words are random node ids (all-zero prob ~ (1/50000)^256).
        int nz = 0;
        #pragma unroll 4
        for (int i = 0; i < 256; i++) nz |= ei32[2 * i + 1];
        g_isI32 = (nz != 0) ? 1 : 0;
    }
    if (tid < n4) ((float4*)g_agg)[tid] = ((const float4*)x)[tid];
    if (tid < 128) g_stats[tid] = 0.0f;
    if (tid < NG * 64) { g_add[tid] = 0.0f; g_max[tid] = 0u; }
}

// ============================================================
// K1: edge scatter  agg[dst] += x[src]
// one thread per (edge, 4-feature chunk): float4 gather + 4 atomics
// ============================================================
__global__ void k_edges(const float* __restrict__ x, const void* __restrict__ ei, int n_edges) {
    int tid = blockIdx.x * blockDim.x + threadIdx.x;
    if (tid >= n_edges * 16) return;
    int e = tid >> 4;
    int c = tid & 15;
    int s, d;
    if (g_isI32) {
        const int* p = (const int*)ei;
        s = p[e]; d = p[n_edges + e];
    } else {
        const long long* p = (const long long*)ei;
        s = (int)p[e]; d = (int)p[n_edges + e];
    }
    float4 v = *(const float4*)(x + (size_t)s * 64 + c * 4);
    float* o = g_agg + (size_t)d * 64 + c * 4;
    atomicAdd(o + 0, v.x);
    atomicAdd(o + 1, v.y);
    atomicAdd(o + 2, v.z);
    atomicAdd(o + 3, v.w);
}

// ============================================================
// K2: h = agg @ W1 + b1, accumulate per-feature sum/sumsq for BN
// 64-row tile per block, 256 threads, 4x4 register blocking
// ============================================================
__global__ __launch_bounds__(256) void k_gemm1(const float* __restrict__ W1,
                                               const float* __restrict__ b1, int n_nodes) {
    __shared__ float sW[64 * 64];
    __shared__ float sA[64 * 68];
    __shared__ float sSum[64], sSq[64];
    int tid = threadIdx.x;
    int row0 = blockIdx.x * 64;

    for (int i = tid; i < 1024; i += 256) ((float4*)sW)[i] = ((const float4*)W1)[i];
    if (tid < 64) { sSum[tid] = 0.0f; sSq[tid] = 0.0f; }
    for (int i = tid; i < 1024; i += 256) {
        int r = i >> 4, c4 = i & 15, gr = row0 + r;
        float4 v = make_float4(0.f, 0.f, 0.f, 0.f);
        if (gr < n_nodes) v = *(const float4*)(g_agg + (size_t)gr * 64 + c4 * 4);
        *(float4*)&sA[r * 68 + c4 * 4] = v;
    }
    __syncthreads();

    int rg = tid >> 4;
    int c0 = (tid & 15) * 4;
    int rbase = rg * 4;
    float acc[4][4];
    float4 bb = *(const float4*)(b1 + c0);
    #pragma unroll
    for (int i = 0; i < 4; i++) { acc[i][0] = bb.x; acc[i][1] = bb.y; acc[i][2] = bb.z; acc[i][3] = bb.w; }

    #pragma unroll 8
    for (int k = 0; k < 64; k++) {
        float4 w = *(const float4*)&sW[k * 64 + c0];
        #pragma unroll
        for (int i = 0; i < 4; i++) {
            float a = sA[(rbase + i) * 68 + k];
            acc[i][0] += a * w.x; acc[i][1] += a * w.y;
            acc[i][2] += a * w.z; acc[i][3] += a * w.w;
        }
    }

    float cs[4] = {0, 0, 0, 0}, cq[4] = {0, 0, 0, 0};
    #pragma unroll
    for (int i = 0; i < 4; i++) {
        int gr = row0 + rbase + i;
        if (gr < n_nodes) {
            *(float4*)(g_h + (size_t)gr * 64 + c0) =
                make_float4(acc[i][0], acc[i][1], acc[i][2], acc[i][3]);
            #pragma unroll
            for (int j = 0; j < 4; j++) { cs[j] += acc[i][j]; cq[j] += acc[i][j] * acc[i][j]; }
        }
    }
    #pragma unroll
    for (int j = 0; j < 4; j++) {
        atomicAdd(&sSum[c0 + j], cs[j]);
        atomicAdd(&sSq[c0 + j], cq[j]);
    }
    __syncthreads();
    if (tid < 64) {
        atomicAdd(&g_stats[tid], sSum[tid]);
        atomicAdd(&g_stats[64 + tid], sSq[tid]);
    }
}

// ============================================================
// K3: BN affine folding
// ============================================================
__global__ void k_stats(const float* __restrict__ gamma, const float* __restrict__ beta, float inv_n) {
    int c = threadIdx.x;
    float mean = g_stats[c] * inv_n;
    float var  = g_stats[64 + c] * inv_n - mean * mean;
    float a = gamma[c] * rsqrtf(var + 1e-5f);
    g_scale[c] = a;
    g_scale[64 + c] = beta[c] - mean * a;
}

// ============================================================
// K4: h2 = relu(relu(bn(h)) @ W2 + b2); pooled into g_add/g_max
// ============================================================
__device__ __forceinline__ void pool_flush(int b, int c0, const float s[4], const float m[4]) {
    float* pa = g_add + (size_t)b * 64 + c0;
    atomicAdd(pa + 0, s[0]); atomicAdd(pa + 1, s[1]);
    atomicAdd(pa + 2, s[2]); atomicAdd(pa + 3, s[3]);
    unsigned* pm = g_max + (size_t)b * 64 + c0;
    atomicMax(pm + 0, __float_as_uint(m[0]));
    atomicMax(pm + 1, __float_as_uint(m[1]));
    atomicMax(pm + 2, __float_as_uint(m[2]));
    atomicMax(pm + 3, __float_as_uint(m[3]));
}

__global__ __launch_bounds__(256) void k_gemm2(const float* __restrict__ W2,
                                               const float* __restrict__ b2,
                                               const void* __restrict__ batch, int n_nodes) {
    __shared__ float sW[64 * 64];
    __shared__ float sA[64 * 68];
    __shared__ float sScale[64], sShift[64];
    int tid = threadIdx.x;
    int row0 = blockIdx.x * 64;

    for (int i = tid; i < 1024; i += 256) ((float4*)sW)[i] = ((const float4*)W2)[i];
    if (tid < 64) { sScale[tid] = g_scale[tid]; sShift[tid] = g_scale[64 + tid]; }
    __syncthreads();
    for (int i = tid; i < 1024; i += 256) {
        int r = i >> 4, c4 = i & 15, gr = row0 + r, k0 = c4 * 4;
        float4 v = make_float4(0.f, 0.f, 0.f, 0.f);
        if (gr < n_nodes) {
            v = *(const float4*)(g_h + (size_t)gr * 64 + k0);
            v.x = fmaxf(v.x * sScale[k0 + 0] + sShift[k0 + 0], 0.f);
            v.y = fmaxf(v.y * sScale[k0 + 1] + sShift[k0 + 1], 0.f);
            v.z = fmaxf(v.z * sScale[k0 + 2] + sShift[k0 + 2], 0.f);
            v.w = fmaxf(v.w * sScale[k0 + 3] + sShift[k0 + 3], 0.f);
        }
        *(float4*)&sA[r * 68 + k0] = v;
    }
    __syncthreads();

    int rg = tid >> 4;
    int c0 = (tid & 15) * 4;
    int rbase = rg * 4;
    float acc[4][4];
    float4 bb = *(const float4*)(b2 + c0);
    #pragma unroll
    for (int i = 0; i < 4; i++) { acc[i][0] = bb.x; acc[i][1] = bb.y; acc[i][2] = bb.z; acc[i][3] = bb.w; }

    #pragma unroll 8
    for (int k = 0; k < 64; k++) {
        float4 w = *(const float4*)&sW[k * 64 + c0];
        #pragma unroll
        for (int i = 0; i < 4; i++) {
            float a = sA[(rbase + i) * 68 + k];
            acc[i][0] += a * w.x; acc[i][1] += a * w.y;
            acc[i][2] += a * w.z; acc[i][3] += a * w.w;
        }
    }

    // fused pooling: merge consecutive rows of the same graph (batch is sorted)
    const int* b32 = (const int*)batch;
    const long long* b64 = (const long long*)batch;
    int isI32 = g_isI32;
    int prevb = -1;
    float s[4] = {0, 0, 0, 0}, m[4] = {0, 0, 0, 0};
    #pragma unroll
    for (int i = 0; i < 4; i++) {
        int gr = row0 + rbase + i;
        if (gr >= n_nodes) break;
        int b = isI32 ? b32[gr] : (int)b64[gr];
        float v[4];
        #pragma unroll
        for (int j = 0; j < 4; j++) v[j] = fmaxf(acc[i][j], 0.f);
        if (b != prevb) {
            if (prevb >= 0) pool_flush(prevb, c0, s, m);
            prevb = b;
            #pragma unroll
            for (int j = 0; j < 4; j++) { s[j] = v[j]; m[j] = v[j]; }
        } else {
            #pragma unroll
            for (int j = 0; j < 4; j++) { s[j] += v[j]; m[j] = fmaxf(m[j], v[j]); }
        }
    }
    if (prevb >= 0) pool_flush(prevb, c0, s, m);
}

// ============================================================
// K5: per-graph head MLP: relu(g @ Wl1 + bl1) @ Wl2 + bl2 -> sigmoid
// one block per graph, 128 threads
// ============================================================
__global__ __launch_bounds__(128) void k_final(const float* __restrict__ Wl1,
                                               const float* __restrict__ bl1,
                                               const float* __restrict__ Wl2,
                                               const float* __restrict__ bl2,
                                               float* __restrict__ out, int out_size) {
    int g = blockIdx.x;
    int j = threadIdx.x;
    __shared__ float sg[128];
    __shared__ float red[128];
    sg[j] = (j < 64) ? g_add[g * 64 + j] : __uint_as_float(g_max[g * 64 + (j - 64)]);
    __syncthreads();
    float t = bl1[j];
    #pragma unroll 8
    for (int k = 0; k < 128; k++) t += sg[k] * Wl1[k * 128 + j];
    t = fmaxf(t, 0.f);
    red[j] = t * Wl2[j];
    __syncthreads();
    for (int sft = 64; sft > 0; sft >>= 1) {
        if (j < sft) red[j] += red[j + sft];
        __syncthreads();
    }
    if (j == 0) {
        float logit = red[0] + bl2[0];
        out[g] = 1.0f / (1.0f + expf(-logit));
        if (out_size >= 2 * (int)gridDim.x) out[gridDim.x + g] = logit;
    }
}

// ============================================================
extern "C" void kernel_launch(void* const* d_in, const int* in_sizes, int n_in,
                              void* d_out, int out_size) {
    const float* x     = (const float*)d_in[0];
    const void*  ei    = d_in[1];
    const void*  batch = d_in[2];
    const float* W1    = (const float*)d_in[3];
    const float* b1    = (const float*)d_in[4];
    const float* gamma = (const float*)d_in[5];
    const float* beta  = (const float*)d_in[6];
    const float* W2    = (const float*)d_in[7];
    const float* b2    = (const float*)d_in[8];
    const float* Wl1   = (const float*)d_in[9];
    const float* bl1   = (const float*)d_in[10];
    const float* Wl2   = (const float*)d_in[11];
    const float* bl2   = (const float*)d_in[12];
    float* out = (float*)d_out;

    int n_nodes = in_sizes[0] / 64;
    if (n_nodes > NMAX) n_nodes = NMAX;
    int n_edges = in_sizes[1] / 2;

    int n4 = n_nodes * 16;
    int initN = (n4 > NG * 64) ? n4 : NG * 64;
    k_init<<<(initN + 255) / 256, 256>>>(x, (const int*)ei, n4);

    long long etot = (long long)n_edges * 16;
    k_edges<<<(int)((etot + 255) / 256), 256>>>(x, ei, n_edges);

    int nb = (n_nodes + 63) / 64;
    k_gemm1<<<nb, 256>>>(W1, b1, n_nodes);
    k_stats<<<1, 64>>>(gamma, beta, 1.0f / (float)n_nodes);
    k_gemm2<<<nb, 256>>>(W2, b2, batch, n_nodes);
    k_final<<<NG, 128>>>(Wl1, bl1, Wl2, bl2, out, out_size);
}

// round 2
// speedup vs baseline: 1.6494x; 1.6494x over previous
#include <cuda_runtime.h>

#define NMAX 50000
#define NG 512

// ---- scratch (static __device__: no allocation allowed) ----
__device__ float    g_agg[NMAX * 64];     // GIN aggregation result
__device__ float    g_h[NMAX * 64];       // hidden after Linear1
__device__ float    g_stats[128];         // [0:64) sum, [64:128) sumsq
__device__ float    g_scale[128];         // [0:64) a = gamma*rstd, [64:128) shift
__device__ float    g_add[NG * 64];       // segment sum pool
__device__ unsigned g_max[NG * 64];       // segment max pool (relu>=0 -> uint order ok)
__device__ int      g_isI32;              // 1 if indices are int32, 0 if int64

// ============================================================
// K0: init agg = x, zero stats & pools, probe index dtype
// ============================================================
__global__ void k_init(const float* __restrict__ x, const int* __restrict__ ei32, int n4) {
    int tid = blockIdx.x * blockDim.x + threadIdx.x;
    if (tid == 0) {
        // If edge_index is int64 (values < 50000), every odd 32-bit word is 0.
        // If int32, odd words are random node ids (all-zero prob ~ (1/50000)^256).
        int nz = 0;
        #pragma unroll 4
        for (int i = 0; i < 256; i++) nz |= ei32[2 * i + 1];
        g_isI32 = (nz != 0) ? 1 : 0;
    }
    if (tid < n4) ((float4*)g_agg)[tid] = ((const float4*)x)[tid];
    if (tid < 128) g_stats[tid] = 0.0f;
    if (tid < NG * 64) { g_add[tid] = 0.0f; g_max[tid] = 0u; }
}

// ============================================================
// K1: edge scatter  agg[dst] += x[src]
// one thread per (edge, 4-feature chunk): float4 gather + 1 vector REDG
// ============================================================
__global__ void k_edges(const float* __restrict__ x, const void* __restrict__ ei, int n_edges) {
    int tid = blockIdx.x * blockDim.x + threadIdx.x;
    if (tid >= n_edges * 16) return;
    int e = tid >> 4;
    int c = tid & 15;
    int s, d;
    if (g_isI32) {
        const int* p = (const int*)ei;
        s = p[e]; d = p[n_edges + e];
    } else {
        const long long* p = (const long long*)ei;
        s = (int)p[e]; d = (int)p[n_edges + e];
    }
    float4 v = *(const float4*)(x + (size_t)s * 64 + c * 4);
    float* o = g_agg + (size_t)d * 64 + c * 4;
    asm volatile("red.global.add.v4.f32 [%0], {%1, %2, %3, %4};"
                 :: "l"(o), "f"(v.x), "f"(v.y), "f"(v.z), "f"(v.w)
                 : "memory");
}

// ============================================================
// K2: h = agg @ W1 + b1, accumulate per-feature sum/sumsq for BN
// 64-row tile per block, 256 threads, 4x4 register blocking
// ============================================================
__global__ __launch_bounds__(256) void k_gemm1(const float* __restrict__ W1,
                                               const float* __restrict__ b1, int n_nodes) {
    __shared__ float sW[64 * 64];
    __shared__ float sA[64 * 68];
    __shared__ float sSum[64], sSq[64];
    int tid = threadIdx.x;
    int row0 = blockIdx.x * 64;

    for (int i = tid; i < 1024; i += 256) ((float4*)sW)[i] = ((const float4*)W1)[i];
    if (tid < 64) { sSum[tid] = 0.0f; sSq[tid] = 0.0f; }
    for (int i = tid; i < 1024; i += 256) {
        int r = i >> 4, c4 = i & 15, gr = row0 + r;
        float4 v = make_float4(0.f, 0.f, 0.f, 0.f);
        if (gr < n_nodes) v = *(const float4*)(g_agg + (size_t)gr * 64 + c4 * 4);
        *(float4*)&sA[r * 68 + c4 * 4] = v;
    }
    __syncthreads();

    int rg = tid >> 4;
    int c0 = (tid & 15) * 4;
    int rbase = rg * 4;
    float acc[4][4];
    float4 bb = *(const float4*)(b1 + c0);
    #pragma unroll
    for (int i = 0; i < 4; i++) { acc[i][0] = bb.x; acc[i][1] = bb.y; acc[i][2] = bb.z; acc[i][3] = bb.w; }

    #pragma unroll 8
    for (int k = 0; k < 64; k++) {
        float4 w = *(const float4*)&sW[k * 64 + c0];
        #pragma unroll
        for (int i = 0; i < 4; i++) {
            float a = sA[(rbase + i) * 68 + k];
            acc[i][0] += a * w.x; acc[i][1] += a * w.y;
            acc[i][2] += a * w.z; acc[i][3] += a * w.w;
        }
    }

    float cs[4] = {0, 0, 0, 0}, cq[4] = {0, 0, 0, 0};
    #pragma unroll
    for (int i = 0; i < 4; i++) {
        int gr = row0 + rbase + i;
        if (gr < n_nodes) {
            *(float4*)(g_h + (size_t)gr * 64 + c0) =
                make_float4(acc[i][0], acc[i][1], acc[i][2], acc[i][3]);
            #pragma unroll
            for (int j = 0; j < 4; j++) { cs[j] += acc[i][j]; cq[j] += acc[i][j] * acc[i][j]; }
        }
    }
    #pragma unroll
    for (int j = 0; j < 4; j++) {
        atomicAdd(&sSum[c0 + j], cs[j]);
        atomicAdd(&sSq[c0 + j], cq[j]);
    }
    __syncthreads();
    if (tid < 64) {
        atomicAdd(&g_stats[tid], sSum[tid]);
        atomicAdd(&g_stats[64 + tid], sSq[tid]);
    }
}

// ============================================================
// K3: BN affine folding
// ============================================================
__global__ void k_stats(const float* __restrict__ gamma, const float* __restrict__ beta, float inv_n) {
    int c = threadIdx.x;
    float mean = g_stats[c] * inv_n;
    float var  = g_stats[64 + c] * inv_n - mean * mean;
    float a = gamma[c] * rsqrtf(var + 1e-5f);
    g_scale[c] = a;
    g_scale[64 + c] = beta[c] - mean * a;
}

// ============================================================
// K4: h2 = relu(relu(bn(h)) @ W2 + b2); pooled into g_add/g_max
// ============================================================
__device__ __forceinline__ void pool_flush(int b, int c0, const float s[4], const float m[4]) {
    float* pa = g_add + (size_t)b * 64 + c0;
    asm volatile("red.global.add.v4.f32 [%0], {%1, %2, %3, %4};"
                 :: "l"(pa), "f"(s[0]), "f"(s[1]), "f"(s[2]), "f"(s[3])
                 : "memory");
    unsigned* pm = g_max + (size_t)b * 64 + c0;
    atomicMax(pm + 0, __float_as_uint(m[0]));
    atomicMax(pm + 1, __float_as_uint(m[1]));
    atomicMax(pm + 2, __float_as_uint(m[2]));
    atomicMax(pm + 3, __float_as_uint(m[3]));
}

__global__ __launch_bounds__(256) void k_gemm2(const float* __restrict__ W2,
                                               const float* __restrict__ b2,
                                               const void* __restrict__ batch, int n_nodes) {
    __shared__ float sW[64 * 64];
    __shared__ float sA[64 * 68];
    __shared__ float sScale[64], sShift[64];
    int tid = threadIdx.x;
    int row0 = blockIdx.x * 64;

    for (int i = tid; i < 1024; i += 256) ((float4*)sW)[i] = ((const float4*)W2)[i];
    if (tid < 64) { sScale[tid] = g_scale[tid]; sShift[tid] = g_scale[64 + tid]; }
    __syncthreads();
    for (int i = tid; i < 1024; i += 256) {
        int r = i >> 4, c4 = i & 15, gr = row0 + r, k0 = c4 * 4;
        float4 v = make_float4(0.f, 0.f, 0.f, 0.f);
        if (gr < n_nodes) {
            v = *(const float4*)(g_h + (size_t)gr * 64 + k0);
            v.x = fmaxf(v.x * sScale[k0 + 0] + sShift[k0 + 0], 0.f);
            v.y = fmaxf(v.y * sScale[k0 + 1] + sShift[k0 + 1], 0.f);
            v.z = fmaxf(v.z * sScale[k0 + 2] + sShift[k0 + 2], 0.f);
            v.w = fmaxf(v.w * sScale[k0 + 3] + sShift[k0 + 3], 0.f);
        }
        *(float4*)&sA[r * 68 + k0] = v;
    }
    __syncthreads();

    int rg = tid >> 4;
    int c0 = (tid & 15) * 4;
    int rbase = rg * 4;
    float acc[4][4];
    float4 bb = *(const float4*)(b2 + c0);
    #pragma unroll
    for (int i = 0; i < 4; i++) { acc[i][0] = bb.x; acc[i][1] = bb.y; acc[i][2] = bb.z; acc[i][3] = bb.w; }

    #pragma unroll 8
    for (int k = 0; k < 64; k++) {
        float4 w = *(const float4*)&sW[k * 64 + c0];
        #pragma unroll
        for (int i = 0; i < 4; i++) {
            float a = sA[(rbase + i) * 68 + k];
            acc[i][0] += a * w.x; acc[i][1] += a * w.y;
            acc[i][2] += a * w.z; acc[i][3] += a * w.w;
        }
    }

    // fused pooling: merge consecutive rows of the same graph (batch is sorted)
    const int* b32 = (const int*)batch;
    const long long* b64 = (const long long*)batch;
    int isI32 = g_isI32;
    int prevb = -1;
    float s[4] = {0, 0, 0, 0}, m[4] = {0, 0, 0, 0};
    #pragma unroll
    for (int i = 0; i < 4; i++) {
        int gr = row0 + rbase + i;
        if (gr >= n_nodes) break;
        int b = isI32 ? b32[gr] : (int)b64[gr];
        float v[4];
        #pragma unroll
        for (int j = 0; j < 4; j++) v[j] = fmaxf(acc[i][j], 0.f);
        if (b != prevb) {
            if (prevb >= 0) pool_flush(prevb, c0, s, m);
            prevb = b;
            #pragma unroll
            for (int j = 0; j < 4; j++) { s[j] = v[j]; m[j] = v[j]; }
        } else {
            #pragma unroll
            for (int j = 0; j < 4; j++) { s[j] += v[j]; m[j] = fmaxf(m[j], v[j]); }
        }
    }
    if (prevb >= 0) pool_flush(prevb, c0, s, m);
}

// ============================================================
// K5: per-graph head MLP: relu(g @ Wl1 + bl1) @ Wl2 + bl2 -> sigmoid
// one block per graph, 128 threads
// ============================================================
__global__ __launch_bounds__(128) void k_final(const float* __restrict__ Wl1,
                                               const float* __restrict__ bl1,
                                               const float* __restrict__ Wl2,
                                               const float* __restrict__ bl2,
                                               float* __restrict__ out, int out_size) {
    int g = blockIdx.x;
    int j = threadIdx.x;
    __shared__ float sg[128];
    __shared__ float red[128];
    sg[j] = (j < 64) ? g_add[g * 64 + j] : __uint_as_float(g_max[g * 64 + (j - 64)]);
    __syncthreads();
    float t = bl1[j];
    #pragma unroll 8
    for (int k = 0; k < 128; k++) t += sg[k] * Wl1[k * 128 + j];
    t = fmaxf(t, 0.f);
    red[j] = t * Wl2[j];
    __syncthreads();
    for (int sft = 64; sft > 0; sft >>= 1) {
        if (j < sft) red[j] += red[j + sft];
        __syncthreads();
    }
    if (j == 0) {
        float logit = red[0] + bl2[0];
        out[g] = 1.0f / (1.0f + expf(-logit));
        if (out_size >= 2 * (int)gridDim.x) out[gridDim.x + g] = logit;
    }
}

// ============================================================
extern "C" void kernel_launch(void* const* d_in, const int* in_sizes, int n_in,
                              void* d_out, int out_size) {
    const float* x     = (const float*)d_in[0];
    const void*  ei    = d_in[1];
    const void*  batch = d_in[2];
    const float* W1    = (const float*)d_in[3];
    const float* b1    = (const float*)d_in[4];
    const float* gamma = (const float*)d_in[5];
    const float* beta  = (const float*)d_in[6];
    const float* W2    = (const float*)d_in[7];
    const float* b2    = (const float*)d_in[8];
    const float* Wl1   = (const float*)d_in[9];
    const float* bl1   = (const float*)d_in[10];
    const float* Wl2   = (const float*)d_in[11];
    const float* bl2   = (const float*)d_in[12];
    float* out = (float*)d_out;

    int n_nodes = in_sizes[0] / 64;
    if (n_nodes > NMAX) n_nodes = NMAX;
    int n_edges = in_sizes[1] / 2;

    int n4 = n_nodes * 16;
    int initN = (n4 > NG * 64) ? n4 : NG * 64;
    k_init<<<(initN + 255) / 256, 256>>>(x, (const int*)ei, n4);

    long long etot = (long long)n_edges * 16;
    k_edges<<<(int)((etot + 255) / 256), 256>>>(x, ei, n_edges);

    int nb = (n_nodes + 63) / 64;
    k_gemm1<<<nb, 256>>>(W1, b1, n_nodes);
    k_stats<<<1, 64>>>(gamma, beta, 1.0f / (float)n_nodes);
    k_gemm2<<<nb, 256>>>(W2, b2, batch, n_nodes);
    k_final<<<NG, 128>>>(Wl1, bl1, Wl2, bl2, out, out_size);
}